// round 9
// baseline (speedup 1.0000x reference)
#include <cuda_runtime.h>
#include <cuda_bf16.h>
#include <cstdint>

#define NN 4096
#define FF 32
#define HF 64
#define CC 10
#define GG 13
#define EE 65536
#define ETOT (EE + NN)   // 69632

// ---------------- scratch (static __device__, no allocation) ----------------
// split-K partial outputs (a = K[0:2048), b = K[2048:4096))
static __device__ __align__(16) float g_g1a[4 * NN * FF], g_g1b[4 * NN * FF];
static __device__ __align__(16) float g_g2a[4 * NN * 96], g_g2b[4 * NN * 96];
static __device__ __align__(16) float g_g3a[NN * 288],    g_g3b[NN * 288];
static __device__ float g_coefs[GG * NN * FF];               // 13 coefficient maps
static __device__ __align__(16) __nv_bfloat16 g_afh[32 * NN],  g_afl[32 * NN];   // |x|^T split
static __device__ __align__(16) __nv_bfloat16 g_a1h[96 * NN],  g_a1l[96 * NN];   // |y1|^T split
static __device__ __align__(16) __nv_bfloat16 g_b3h[288 * NN], g_b3l[288 * NN];  // |y2|^T split
static __device__ float g_h[(size_t)GG * NN * HF];           // GAT h per branch
static __device__ float g_es[GG * NN * 2];
static __device__ float g_ed[GG * NN * 2];
static __device__ float g_feat[(size_t)NN * GG * HF];        // concat branch MLP outputs
static __device__ int   g_off[NN + 1];
static __device__ int   g_cur[NN];
static __device__ int   g_csrc[ETOT];

// ---------------- helpers ----------------
__device__ __forceinline__ void bf16split(float v, __nv_bfloat16& h, __nv_bfloat16& l) {
    h = __float2bfloat16_rn(v);
    l = __float2bfloat16_rn(v - __bfloat162float(h));
}
__device__ __forceinline__ uint32_t pk(__nv_bfloat16 a, __nv_bfloat16 b) {
    __nv_bfloat162 t = __halves2bfloat162(a, b);
    return *reinterpret_cast<uint32_t*>(&t);
}
__device__ __forceinline__ uint32_t s2u(const void* p) {
    uint32_t a;
    asm("{ .reg .u64 t; cvta.to.shared.u64 t, %1; cvt.u32.u64 %0, t; }" : "=r"(a) : "l"(p));
    return a;
}

#define CP_ASYNC16(saddr, gaddr) \
    asm volatile("cp.async.cg.shared.global [%0], [%1], 16;" :: "r"(saddr), "l"(gaddr))
#define CP_COMMIT() asm volatile("cp.async.commit_group;" ::: "memory")
#define CP_WAIT1()  asm volatile("cp.async.wait_group 1;" ::: "memory")

#define LDMX4(r0, r1, r2, r3, a) \
    asm volatile("ldmatrix.sync.aligned.m8n8.x4.shared.b16 {%0,%1,%2,%3}, [%4];" \
                 : "=r"(r0), "=r"(r1), "=r"(r2), "=r"(r3) : "r"(a))
#define MMA16816(c, a0, a1, a2, a3, b0, b1) \
    asm volatile("mma.sync.aligned.m16n8k16.row.col.f32.bf16.bf16.f32 " \
                 "{%0,%1,%2,%3}, {%4,%5,%6,%7}, {%8,%9}, {%0,%1,%2,%3};" \
                 : "+f"((c)[0]), "+f"((c)[1]), "+f"((c)[2]), "+f"((c)[3]) \
                 : "r"(a0), "r"(a1), "r"(a2), "r"(a3), "r"(b0), "r"(b1))

// ---------------- transpose + abs + bf16-split repack kernels ----------------
__global__ void k_absT(const float* __restrict__ x) {
    __shared__ float s[32][33];
    int n0 = blockIdx.x * 32;
    int tx = threadIdx.x, ty = threadIdx.y;
    #pragma unroll
    for (int i = 0; i < 4; i++)
        s[ty + 8 * i][tx] = fabsf(x[(size_t)(n0 + ty + 8 * i) * 32 + tx]);
    __syncthreads();
    #pragma unroll
    for (int i = 0; i < 4; i++) {
        int f = ty + 8 * i;
        __nv_bfloat16 h, l; bf16split(s[tx][f], h, l);
        g_afh[(size_t)f * NN + n0 + tx] = h;
        g_afl[(size_t)f * NN + n0 + tx] = l;
    }
}

__global__ void k_a1T() {
    __shared__ float s[32][33];
    int n0 = blockIdx.x * 32, j = blockIdx.y;
    int tx = threadIdx.x, ty = threadIdx.y;
    #pragma unroll
    for (int i = 0; i < 4; i++) {
        size_t idx = ((size_t)(1 + j) * NN + n0 + ty + 8 * i) * 32 + tx;
        s[ty + 8 * i][tx] = fabsf(g_g1a[idx] + g_g1b[idx]);
    }
    __syncthreads();
    #pragma unroll
    for (int i = 0; i < 4; i++) {
        int f = ty + 8 * i;
        __nv_bfloat16 h, l; bf16split(s[tx][f], h, l);
        g_a1h[(size_t)(j * 32 + f) * NN + n0 + tx] = h;
        g_a1l[(size_t)(j * 32 + f) * NN + n0 + tx] = l;
    }
}

__global__ void k_b3T() {
    __shared__ float s[32][33];
    int n0 = blockIdx.x * 32, y = blockIdx.y;          // y = j*3 + k
    int j = y / 3, k = y - 3 * j;
    int tx = threadIdx.x, ty = threadIdx.y;
    #pragma unroll
    for (int i = 0; i < 4; i++) {
        size_t idx = ((size_t)(1 + k) * NN + n0 + ty + 8 * i) * 96 + j * 32 + tx;
        s[ty + 8 * i][tx] = fabsf(g_g2a[idx] + g_g2b[idx]);
    }
    __syncthreads();
    #pragma unroll
    for (int i = 0; i < 4; i++) {
        int f = ty + 8 * i;
        __nv_bfloat16 h, l; bf16split(s[tx][f], h, l);
        g_b3h[(size_t)(y * 32 + f) * NN + n0 + tx] = h;
        g_b3l[(size_t)(y * 32 + f) * NN + n0 + tx] = l;
    }
}

__global__ void k_coefs() {
    int i = blockIdx.x * 256 + threadIdx.x;            // GG*NN*FF
    int g = i / (NN * FF);
    int r = i - g * (NN * FF);
    int n = r >> 5, f = r & 31;
    float v;
    if (g == 0) {
        size_t idx = (size_t)n * FF + f;
        v = g_g1a[idx] + g_g1b[idx];
    } else if (g < 4) {
        size_t idx = (size_t)n * 96 + (g - 1) * 32 + f;
        v = g_g2a[idx] + g_g2b[idx];
    } else {
        size_t idx = (size_t)n * 288 + (g - 4) * 32 + f;
        v = g_g3a[idx] + g_g3b[idx];
    }
    g_coefs[i] = v;
}

// ---------------- mma.sync 3xBF16 GEMM, split-K=2 ----------------
// Block tile 128 x BN, K-stage 32, 8 warps (R=4 x C=2). blockIdx.z selects the
// K half (2048 each) and the partial output buffer. 87KB smem (BN=96) ->
// 2 CTAs/SM so barrier bubbles in one CTA are covered by the other.
template<int BN>
__global__ void __launch_bounds__(256, 2)
k_gemm_mma(const float* __restrict__ U, const float* __restrict__ psi,
           int usepsi, int sel, int ldc)
{
    extern __shared__ __align__(16) char sm[];
    constexpr int AP   = 80;                 // 64B row + 16 pad -> conflict-free ldmatrix
    constexpr int ASZ  = 128 * AP;           // one A operand (hi or lo)
    constexpr int ASTG = 2 * ASZ;            // A stage: Ahi | Alo
    constexpr int BSZ  = BN * AP;
    constexpr int BSTG = 2 * BSZ;            // B stage: Bhi | Blo
    constexpr int BOFF = 2 * ASTG;           // B region after 2 A stages
    constexpr int CW   = BN / 2;             // cols per warp
    constexpr int NT   = CW / 8;
    constexpr int NP   = NT / 2;
    constexpr int BCHK = BN * 4;             // 16B chunks per operand per stage
    constexpr int NIT  = 64;                 // 2048 / 32

    const int tid = threadIdx.x;
    const int warp = tid >> 5, lane = tid & 31;
    const int rw = warp & 3;                 // row group (32 rows)
    const int chh = warp >> 2;               // N half
    const int K = 4096;
    const int row0 = blockIdx.x * 128;
    const int col0 = blockIdx.y * BN;
    const int k0 = blockIdx.z * 2048;
    const float* __restrict__ A = ((usepsi && row0 >= NN) ? psi + (size_t)(row0 - NN) * K
                                                          : U + (size_t)row0 * K) + k0;
    const __nv_bfloat16 *Bh, *Bl;
    float* C;
    if (sel == 0)      { Bh = g_afh; Bl = g_afl; C = blockIdx.z ? g_g1b : g_g1a; }
    else if (sel == 1) { Bh = g_a1h; Bl = g_a1l; C = blockIdx.z ? g_g2b : g_g2a; }
    else               { Bh = g_b3h; Bl = g_b3l; C = blockIdx.z ? g_g3b : g_g3a; }

    float c[2][NT][4];
    #pragma unroll
    for (int m = 0; m < 2; m++)
        #pragma unroll
        for (int j = 0; j < NT; j++)
            #pragma unroll
            for (int q = 0; q < 4; q++) c[m][j][q] = 0.f;

    // per-thread A mapping over the 128x32 fp32 tile: 4 x float4, rows step 32
    const int am_r = tid >> 3;               // 0..31
    const int am_c = (tid & 7) * 4;          // 0..28

    float4 areg[4];
    #pragma unroll
    for (int i = 0; i < 4; i++)
        areg[i] = *reinterpret_cast<const float4*>(A + (size_t)(am_r + 32 * i) * K + am_c);

    uint32_t sbase = s2u(sm);

    // B(0) cp.async -> B stage 0
    #pragma unroll
    for (int i = 0; i < BN / 32; i++) {
        int q = tid + i * 256;
        int half = q >= BCHK;
        int qq = q - half * BCHK;
        int n = qq >> 2, c16 = qq & 3;
        const __nv_bfloat16* src = (half ? Bl : Bh) + (size_t)(col0 + n) * 4096 + k0 + c16 * 8;
        CP_ASYNC16(sbase + BOFF + half * BSZ + n * AP + c16 * 16, src);
    }
    CP_COMMIT();

    // STS A(0) into A stage 0
    #pragma unroll
    for (int i = 0; i < 4; i++) {
        int r = am_r + 32 * i;
        __nv_bfloat16 h0, h1, h2, h3, l0, l1, l2, l3;
        bf16split(areg[i].x, h0, l0); bf16split(areg[i].y, h1, l1);
        bf16split(areg[i].z, h2, l2); bf16split(areg[i].w, h3, l3);
        *reinterpret_cast<uint2*>(sm + r * AP + am_c * 2) = make_uint2(pk(h0, h1), pk(h2, h3));
        *reinterpret_cast<uint2*>(sm + ASZ + r * AP + am_c * 2) = make_uint2(pk(l0, l1), pk(l2, l3));
    }

    // A(1) prefetch + B(1) cp.async -> B stage 1
    #pragma unroll
    for (int i = 0; i < 4; i++)
        areg[i] = *reinterpret_cast<const float4*>(A + (size_t)(am_r + 32 * i) * K + 32 + am_c);
    #pragma unroll
    for (int i = 0; i < BN / 32; i++) {
        int q = tid + i * 256;
        int half = q >= BCHK;
        int qq = q - half * BCHK;
        int n = qq >> 2, c16 = qq & 3;
        const __nv_bfloat16* src = (half ? Bl : Bh) + (size_t)(col0 + n) * 4096 + k0 + 32 + c16 * 8;
        CP_ASYNC16(sbase + BOFF + BSTG + half * BSZ + n * AP + c16 * 16, src);
    }
    CP_COMMIT();

    // ldmatrix lane addressing (within-stage byte offsets)
    const int a_off0 = (rw * 32 + (lane & 15)) * AP + (lane >> 4) * 16;
    const int a_off1 = a_off0 + 16 * AP;
    const int b_off  = (chh * CW + (lane & 7) + ((lane >> 4) << 3)) * AP +
                       ((lane >> 3) & 1) * 16;

    int bs = 0;                                   // B stage for iter it (= it % 3)
    for (int it = 0; it < NIT; ++it) {
        CP_WAIT1();                               // B(it) landed (B(it+1) may fly)
        __syncthreads();                          // A(it) STS + prior-stage reads fenced

        char* abuf = sm + (it & 1) * ASTG;
        char* nbuf = sm + ((it + 1) & 1) * ASTG;
        uint32_t a0addr = s2u(abuf) + a_off0;
        uint32_t a1addr = s2u(abuf) + a_off1;
        uint32_t bhaddr = sbase + BOFF + bs * BSTG + b_off;
        uint32_t bladdr = bhaddr + BSZ;
        int bt = bs + 2; if (bt >= 3) bt -= 3;    // B stage for it+2

        #pragma unroll
        for (int ks = 0; ks < 2; ks++) {
            uint32_t x0h0, x0h1, x0h2, x0h3, x0l0, x0l1, x0l2, x0l3;
            uint32_t x1h0, x1h1, x1h2, x1h3, x1l0, x1l1, x1l2, x1l3;
            LDMX4(x0h0, x0h1, x0h2, x0h3, a0addr + ks * 32);
            LDMX4(x0l0, x0l1, x0l2, x0l3, a0addr + ASZ + ks * 32);
            LDMX4(x1h0, x1h1, x1h2, x1h3, a1addr + ks * 32);
            LDMX4(x1l0, x1l1, x1l2, x1l3, a1addr + ASZ + ks * 32);
            #pragma unroll
            for (int jp = 0; jp < NP; jp++) {
                uint32_t bh0, bh1, bh2, bh3, bl0, bl1, bl2, bl3;
                LDMX4(bh0, bh1, bh2, bh3, bhaddr + jp * (16 * AP) + ks * 32);
                LDMX4(bl0, bl1, bl2, bl3, bladdr + jp * (16 * AP) + ks * 32);
                MMA16816(c[0][2 * jp],     x0h0, x0h1, x0h2, x0h3, bh0, bh1);
                MMA16816(c[0][2 * jp],     x0h0, x0h1, x0h2, x0h3, bl0, bl1);
                MMA16816(c[0][2 * jp],     x0l0, x0l1, x0l2, x0l3, bh0, bh1);
                MMA16816(c[1][2 * jp],     x1h0, x1h1, x1h2, x1h3, bh0, bh1);
                MMA16816(c[1][2 * jp],     x1h0, x1h1, x1h2, x1h3, bl0, bl1);
                MMA16816(c[1][2 * jp],     x1l0, x1l1, x1l2, x1l3, bh0, bh1);
                MMA16816(c[0][2 * jp + 1], x0h0, x0h1, x0h2, x0h3, bh2, bh3);
                MMA16816(c[0][2 * jp + 1], x0h0, x0h1, x0h2, x0h3, bl2, bl3);
                MMA16816(c[0][2 * jp + 1], x0l0, x0l1, x0l2, x0l3, bh2, bh3);
                MMA16816(c[1][2 * jp + 1], x1h0, x1h1, x1h2, x1h3, bh2, bh3);
                MMA16816(c[1][2 * jp + 1], x1h0, x1h1, x1h2, x1h3, bl2, bl3);
                MMA16816(c[1][2 * jp + 1], x1l0, x1l1, x1l2, x1l3, bh2, bh3);
            }
            // interleaved pipeline work (disjoint smem stages, no barrier needed)
            if (ks == 0) {
                // STS A(it+1) into next A stage
                #pragma unroll
                for (int i = 0; i < 4; i++) {
                    int r = am_r + 32 * i;
                    __nv_bfloat16 h0, h1, h2, h3, l0, l1, l2, l3;
                    bf16split(areg[i].x, h0, l0); bf16split(areg[i].y, h1, l1);
                    bf16split(areg[i].z, h2, l2); bf16split(areg[i].w, h3, l3);
                    *reinterpret_cast<uint2*>(nbuf + r * AP + am_c * 2) =
                        make_uint2(pk(h0, h1), pk(h2, h3));
                    *reinterpret_cast<uint2*>(nbuf + ASZ + r * AP + am_c * 2) =
                        make_uint2(pk(l0, l1), pk(l2, l3));
                }
            } else {
                if (it < NIT - 2) {
                    int kt = (it + 2) * 32;
                    #pragma unroll
                    for (int i = 0; i < 4; i++)
                        areg[i] = *reinterpret_cast<const float4*>(
                            A + (size_t)(am_r + 32 * i) * K + kt + am_c);
                    uint32_t sb = sbase + BOFF + bt * BSTG;
                    #pragma unroll
                    for (int i = 0; i < BN / 32; i++) {
                        int q = tid + i * 256;
                        int half = q >= BCHK;
                        int qq = q - half * BCHK;
                        int n = qq >> 2, c16 = qq & 3;
                        const __nv_bfloat16* src = (half ? Bl : Bh) +
                            (size_t)(col0 + n) * 4096 + k0 + kt + c16 * 8;
                        CP_ASYNC16(sb + half * BSZ + n * AP + c16 * 16, src);
                    }
                }
                CP_COMMIT();                      // unconditional: keeps group count exact
            }
        }
        if (++bs == 3) bs = 0;
    }

    // epilogue
    #pragma unroll
    for (int m = 0; m < 2; m++) {
        int rlo = row0 + rw * 32 + m * 16 + lane / 4;
        int rhi = rlo + 8;
        #pragma unroll
        for (int j = 0; j < NT; j++) {
            int col = col0 + chh * CW + j * 8 + (lane & 3) * 2;
            *reinterpret_cast<float2*>(C + (size_t)rlo * ldc + col) =
                make_float2(c[m][j][0], c[m][j][1]);
            *reinterpret_cast<float2*>(C + (size_t)rhi * ldc + col) =
                make_float2(c[m][j][2], c[m][j][3]);
        }
    }
}

// ---------------- CSR build (by dst, with self loops) ----------------
__global__ void k_csr_init() {
    int i = blockIdx.x * 256 + threadIdx.x;
    if (i < NN) g_cur[i] = 1;
}

__global__ void k_csr_hist(const int* __restrict__ ei) {
    int i = blockIdx.x * 256 + threadIdx.x;
    atomicAdd(&g_cur[ei[EE + i]], 1);
}

__global__ void __launch_bounds__(1024) k_csr_scan() {
    int t = threadIdx.x;
    int b = t * 4;
    int c0 = g_cur[b], c1 = g_cur[b + 1], c2 = g_cur[b + 2], c3 = g_cur[b + 3];
    int s1 = c0 + c1, s2 = s1 + c2, tot = s2 + c3;
    int lane = t & 31, wid = t >> 5;
    int x = tot;
    #pragma unroll
    for (int o = 1; o < 32; o <<= 1) {
        int y = __shfl_up_sync(0xffffffffu, x, o);
        if (lane >= o) x += y;
    }
    __shared__ int ws[32];
    if (lane == 31) ws[wid] = x;
    __syncthreads();
    if (wid == 0) {
        int y = ws[lane];
        #pragma unroll
        for (int o = 1; o < 32; o <<= 1) {
            int z = __shfl_up_sync(0xffffffffu, y, o);
            if (lane >= o) y += z;
        }
        ws[lane] = y;
    }
    __syncthreads();
    int excl = x - tot + (wid ? ws[wid - 1] : 0);
    g_off[b] = excl; g_off[b + 1] = excl + c0; g_off[b + 2] = excl + s1; g_off[b + 3] = excl + s2;
    g_cur[b] = excl; g_cur[b + 1] = excl + c0; g_cur[b + 2] = excl + s1; g_cur[b + 3] = excl + s2;
    if (t == 1023) g_off[NN] = excl + tot;
}

__global__ void k_csr_scatter(const int* __restrict__ ei) {
    int i = blockIdx.x * 256 + threadIdx.x;
    int s, d;
    if (i < EE) { s = ei[i]; d = ei[EE + i]; }
    else        { s = d = i - EE; }
    int pos = atomicAdd(&g_cur[d], 1);
    g_csrc[pos] = s;
}

// ---------------- GAT h/es/ed: warp-per-16-nodes, no smem, no syncs ---------
__global__ void __launch_bounds__(256)
k_h(const float* __restrict__ gat_W, const float* __restrict__ att_src,
    const float* __restrict__ att_dst)
{
    int g = blockIdx.y;
    int warp = threadIdx.x >> 5, lane = threadIdx.x & 31;
    int n0 = (blockIdx.x * 8 + warp) * 16;
    float w0[32], w1[32];
    #pragma unroll
    for (int k = 0; k < 32; k++) {
        w0[k] = gat_W[(size_t)g * 2048 + k * 64 + lane];
        w1[k] = gat_W[(size_t)g * 2048 + k * 64 + lane + 32];
    }
    float as0 = att_src[g * 64 + lane], as1 = att_src[g * 64 + lane + 32];
    float ad0 = att_dst[g * 64 + lane], ad1 = att_dst[g * 64 + lane + 32];
    for (int t = 0; t < 16; t++) {
        int n = n0 + t;
        float cof = g_coefs[((size_t)g * NN + n) * FF + lane];
        float acc0 = 0.f, acc1 = 0.f;
        #pragma unroll
        for (int k = 0; k < 32; k++) {
            float c = __shfl_sync(0xffffffffu, cof, k);
            acc0 += w0[k] * c;
            acc1 += w1[k] * c;
        }
        g_h[((size_t)g * NN + n) * HF + lane]      = acc0;
        g_h[((size_t)g * NN + n) * HF + lane + 32] = acc1;
        float vs0 = acc0 * as0, vs1 = acc1 * as1;
        float vd0 = acc0 * ad0, vd1 = acc1 * ad1;
        #pragma unroll
        for (int o = 16; o; o >>= 1) {
            vs0 += __shfl_xor_sync(0xffffffffu, vs0, o);
            vs1 += __shfl_xor_sync(0xffffffffu, vs1, o);
            vd0 += __shfl_xor_sync(0xffffffffu, vd0, o);
            vd1 += __shfl_xor_sync(0xffffffffu, vd1, o);
        }
        if (lane == 0) {
            *reinterpret_cast<float2*>(&g_es[((size_t)g * NN + n) * 2]) = make_float2(vs0, vs1);
            *reinterpret_cast<float2*>(&g_ed[((size_t)g * NN + n) * 2]) = make_float2(vd0, vd1);
        }
    }
}

// ---------------- GAT aggregation + branch MLP: warp per (node,branch) ------
// Online softmax (running max/z/acc with rescale) -> single pass over edges,
// zero intra-block syncs in the edge loop. Lane handles features f and f+32.
// Branch MLP via 32 shfl broadcasts against smem-cached W_g.
__global__ void __launch_bounds__(256)
k_agg(const float* __restrict__ gat_b, const float* __restrict__ mlp_W,
      const float* __restrict__ mlp_b)
{
    int g = blockIdx.y;
    int warp = threadIdx.x >> 5, lane = threadIdx.x & 31;
    int n = blockIdx.x * 8 + warp;

    __shared__ float Ws[64 * 64];
    __shared__ float gbs[64], mbs[64];
    for (int i = threadIdx.x; i < 64 * 64; i += 256)
        Ws[i] = mlp_W[(size_t)g * 4096 + i];
    if (threadIdx.x < 64) {
        gbs[threadIdx.x] = gat_b[g * 64 + threadIdx.x];
        mbs[threadIdx.x] = mlp_b[g * 64 + threadIdx.x];
    }
    __syncthreads();

    int beg = g_off[n], deg = g_off[n + 1] - beg;
    float2 edn = *reinterpret_cast<const float2*>(&g_ed[((size_t)g * NN + n) * 2]);
    const float* hb = &g_h[(size_t)g * NN * HF];

    float m0 = -1e30f, m1 = -1e30f, z0 = 0.f, z1 = 0.f, a0 = 0.f, a1 = 0.f;
    for (int i = 0; i < deg; i++) {
        int s = g_csrc[beg + i];
        float2 e = *reinterpret_cast<const float2*>(&g_es[((size_t)g * NN + s) * 2]);
        float e0 = e.x + edn.x; e0 = e0 > 0.f ? e0 : 0.2f * e0;
        float e1 = e.y + edn.y; e1 = e1 > 0.f ? e1 : 0.2f * e1;
        float h0 = hb[(size_t)s * HF + lane];
        float h1 = hb[(size_t)s * HF + lane + 32];
        float nm0 = fmaxf(m0, e0), nm1 = fmaxf(m1, e1);
        float r0 = expf(m0 - nm0), r1 = expf(m1 - nm1);
        float w0 = expf(e0 - nm0), w1 = expf(e1 - nm1);
        z0 = z0 * r0 + w0;           z1 = z1 * r1 + w1;
        a0 = a0 * r0 + w0 * h0;      a1 = a1 * r1 + w1 * h1;
        m0 = nm0;                    m1 = nm1;
    }

    float v0 = a0 / (z0 + 1e-16f) + gbs[lane];
    float v1 = a1 / (z1 + 1e-16f) + gbs[lane + 32];
    v0 = v0 > 0.f ? v0 : expm1f(v0);
    v1 = v1 > 0.f ? v1 : expm1f(v1);

    float oA = mbs[lane], oB = mbs[lane + 32];
    #pragma unroll
    for (int k = 0; k < 32; k++) {
        float c0 = __shfl_sync(0xffffffffu, v0, k);
        float c1 = __shfl_sync(0xffffffffu, v1, k);
        oA += c0 * Ws[k * 64 + lane]        + c1 * Ws[(k + 32) * 64 + lane];
        oB += c0 * Ws[k * 64 + lane + 32]   + c1 * Ws[(k + 32) * 64 + lane + 32];
    }
    g_feat[(size_t)n * (GG * HF) + g * HF + lane]      = oA;
    g_feat[(size_t)n * (GG * HF) + g * HF + lane + 32] = oB;
}

// ---------------- final head + log_softmax ----------------
__global__ void __launch_bounds__(128)
k_out(const float* __restrict__ out_W, const float* __restrict__ out_b,
      float* __restrict__ out)
{
    int node = blockIdx.x * 4 + (threadIdx.x >> 5);
    int lane = threadIdx.x & 31;
    float acc[CC];
    #pragma unroll
    for (int c = 0; c < CC; c++) acc[c] = 0.f;
    const float* fr = &g_feat[(size_t)node * (GG * HF)];
    for (int k = lane; k < GG * HF; k += 32) {
        float v = fr[k];
        v = v > 0.f ? v : expm1f(v);
        #pragma unroll
        for (int c = 0; c < CC; c++) acc[c] += v * out_W[k * CC + c];
    }
    #pragma unroll
    for (int c = 0; c < CC; c++) {
        #pragma unroll
        for (int o = 16; o; o >>= 1)
            acc[c] += __shfl_xor_sync(0xffffffffu, acc[c], o);
        acc[c] += out_b[c];
    }
    float m = acc[0];
    #pragma unroll
    for (int c = 1; c < CC; c++) m = fmaxf(m, acc[c]);
    float s = 0.f;
    #pragma unroll
    for (int c = 0; c < CC; c++) s += expf(acc[c] - m);
    float lse = m + logf(s);
    if (lane < CC) out[(size_t)node * CC + lane] = acc[lane] - lse;
}

// ---------------- launcher ----------------
extern "C" void kernel_launch(void* const* d_in, const int* in_sizes, int n_in,
                              void* d_out, int out_size)
{
    const float* x       = (const float*)d_in[0];
    const int*   ei      = (const int*)  d_in[1];
    const float* U       = (const float*)d_in[2];
    const float* psi     = (const float*)d_in[3];
    const float* gat_W   = (const float*)d_in[4];
    const float* att_src = (const float*)d_in[5];
    const float* att_dst = (const float*)d_in[6];
    const float* gat_b   = (const float*)d_in[7];
    const float* mlp_W   = (const float*)d_in[8];
    const float* mlp_b   = (const float*)d_in[9];
    const float* out_W   = (const float*)d_in[10];
    const float* out_b   = (const float*)d_in[11];
    float* out = (float*)d_out;

    // smem: 2 A stages (2*2*128*80) + 3 B stages (3*2*BN*80)
    constexpr int SM32 = 4 * 128 * 80 + 6 * 32 * 80;    // 56320
    constexpr int SM96 = 4 * 128 * 80 + 6 * 96 * 80;    // 87040
    cudaFuncSetAttribute((const void*)k_gemm_mma<32>,
                         cudaFuncAttributeMaxDynamicSharedMemorySize, SM32);
    cudaFuncSetAttribute((const void*)k_gemm_mma<96>,
                         cudaFuncAttributeMaxDynamicSharedMemorySize, SM96);

    // scattering-tree GEMM chain first (mma.sync, 3xBF16, split-K=2)
    k_absT<<<128, dim3(32, 8)>>>(x);
    k_gemm_mma<32><<<dim3(128, 1, 2), 256, SM32>>>(U, psi, 1, 0, 32);   // [U;psi]@af
    k_a1T<<<dim3(128, 3), dim3(32, 8)>>>();
    k_gemm_mma<96><<<dim3(128, 1, 2), 256, SM96>>>(U, psi, 1, 1, 96);   // [U;psi]@|y1|
    k_b3T<<<dim3(128, 9), dim3(32, 8)>>>();
    k_gemm_mma<96><<<dim3(32, 3, 2), 256, SM96>>>(U, psi, 0, 2, 288);   // U@|y2|
    k_coefs<<<(GG * NN * FF) / 256, 256>>>();

    // CSR build (only needed before k_agg)
    k_csr_init<<<16, 256>>>();
    k_csr_hist<<<EE / 256, 256>>>(ei);
    k_csr_scan<<<1, 1024>>>();
    k_csr_scatter<<<ETOT / 256, 256>>>(ei);

    // GAT branches + MLPs
    k_h<<<dim3(NN / 128, GG), 256>>>(gat_W, att_src, att_dst);
    k_agg<<<dim3(NN / 8, GG), 256>>>(gat_b, mlp_W, mlp_b);

    // final head + log_softmax
    k_out<<<NN / 4, 128>>>(out_W, out_b, out);
}

// round 10
// speedup vs baseline: 1.0464x; 1.0464x over previous
#include <cuda_runtime.h>
#include <cuda_bf16.h>
#include <cstdint>

#define NN 4096
#define FF 32
#define HF 64
#define CC 10
#define GG 13
#define EE 65536
#define ETOT (EE + NN)   // 69632

// ---------------- scratch (static __device__, no allocation) ----------------
// split-K partial outputs (a = K[0:2048), b = K[2048:4096))
static __device__ __align__(16) float g_g1a[4 * NN * FF], g_g1b[4 * NN * FF];
static __device__ __align__(16) float g_g2a[4 * NN * 96], g_g2b[4 * NN * 96];
static __device__ __align__(16) float g_g3a[NN * 288],    g_g3b[NN * 288];
static __device__ __align__(16) __nv_bfloat16 g_afh[32 * NN],  g_afl[32 * NN];   // |x|^T split
static __device__ __align__(16) __nv_bfloat16 g_a1h[96 * NN],  g_a1l[96 * NN];   // |y1|^T split
static __device__ __align__(16) __nv_bfloat16 g_b3h[288 * NN], g_b3l[288 * NN];  // |y2|^T split
static __device__ float g_h[(size_t)GG * NN * HF];           // GAT h per branch
static __device__ float g_es[GG * NN * 2];
static __device__ float g_ed[GG * NN * 2];
static __device__ float g_feat[(size_t)NN * GG * HF];        // concat branch MLP outputs
static __device__ int   g_off[NN + 1];
static __device__ int   g_cur[NN];
static __device__ int   g_csrc[ETOT];

// ---------------- helpers ----------------
__device__ __forceinline__ void bf16split(float v, __nv_bfloat16& h, __nv_bfloat16& l) {
    h = __float2bfloat16_rn(v);
    l = __float2bfloat16_rn(v - __bfloat162float(h));
}
__device__ __forceinline__ uint32_t pk(__nv_bfloat16 a, __nv_bfloat16 b) {
    __nv_bfloat162 t = __halves2bfloat162(a, b);
    return *reinterpret_cast<uint32_t*>(&t);
}
__device__ __forceinline__ uint32_t s2u(const void* p) {
    uint32_t a;
    asm("{ .reg .u64 t; cvta.to.shared.u64 t, %1; cvt.u32.u64 %0, t; }" : "=r"(a) : "l"(p));
    return a;
}

#define CP_ASYNC16(saddr, gaddr) \
    asm volatile("cp.async.cg.shared.global [%0], [%1], 16;" :: "r"(saddr), "l"(gaddr))
#define CP_COMMIT() asm volatile("cp.async.commit_group;" ::: "memory")
#define CP_WAIT1()  asm volatile("cp.async.wait_group 1;" ::: "memory")

#define LDMX4(r0, r1, r2, r3, a) \
    asm volatile("ldmatrix.sync.aligned.m8n8.x4.shared.b16 {%0,%1,%2,%3}, [%4];" \
                 : "=r"(r0), "=r"(r1), "=r"(r2), "=r"(r3) : "r"(a))
#define MMA16816(c, a0, a1, a2, a3, b0, b1) \
    asm volatile("mma.sync.aligned.m16n8k16.row.col.f32.bf16.bf16.f32 " \
                 "{%0,%1,%2,%3}, {%4,%5,%6,%7}, {%8,%9}, {%0,%1,%2,%3};" \
                 : "+f"((c)[0]), "+f"((c)[1]), "+f"((c)[2]), "+f"((c)[3]) \
                 : "r"(a0), "r"(a1), "r"(a2), "r"(a3), "r"(b0), "r"(b1))

// ---------------- transpose + abs + bf16-split repack kernels ----------------
__global__ void k_absT(const float* __restrict__ x) {
    __shared__ float s[32][33];
    int n0 = blockIdx.x * 32;
    int tx = threadIdx.x, ty = threadIdx.y;
    #pragma unroll
    for (int i = 0; i < 4; i++)
        s[ty + 8 * i][tx] = fabsf(x[(size_t)(n0 + ty + 8 * i) * 32 + tx]);
    __syncthreads();
    #pragma unroll
    for (int i = 0; i < 4; i++) {
        int f = ty + 8 * i;
        __nv_bfloat16 h, l; bf16split(s[tx][f], h, l);
        g_afh[(size_t)f * NN + n0 + tx] = h;
        g_afl[(size_t)f * NN + n0 + tx] = l;
    }
}

__global__ void k_a1T() {
    __shared__ float s[32][33];
    int n0 = blockIdx.x * 32, j = blockIdx.y;
    int tx = threadIdx.x, ty = threadIdx.y;
    #pragma unroll
    for (int i = 0; i < 4; i++) {
        size_t idx = ((size_t)(1 + j) * NN + n0 + ty + 8 * i) * 32 + tx;
        s[ty + 8 * i][tx] = fabsf(g_g1a[idx] + g_g1b[idx]);
    }
    __syncthreads();
    #pragma unroll
    for (int i = 0; i < 4; i++) {
        int f = ty + 8 * i;
        __nv_bfloat16 h, l; bf16split(s[tx][f], h, l);
        g_a1h[(size_t)(j * 32 + f) * NN + n0 + tx] = h;
        g_a1l[(size_t)(j * 32 + f) * NN + n0 + tx] = l;
    }
}

__global__ void k_b3T() {
    __shared__ float s[32][33];
    int n0 = blockIdx.x * 32, y = blockIdx.y;          // y = j*3 + k
    int j = y / 3, k = y - 3 * j;
    int tx = threadIdx.x, ty = threadIdx.y;
    #pragma unroll
    for (int i = 0; i < 4; i++) {
        size_t idx = ((size_t)(1 + k) * NN + n0 + ty + 8 * i) * 96 + j * 32 + tx;
        s[ty + 8 * i][tx] = fabsf(g_g2a[idx] + g_g2b[idx]);
    }
    __syncthreads();
    #pragma unroll
    for (int i = 0; i < 4; i++) {
        int f = ty + 8 * i;
        __nv_bfloat16 h, l; bf16split(s[tx][f], h, l);
        g_b3h[(size_t)(y * 32 + f) * NN + n0 + tx] = h;
        g_b3l[(size_t)(y * 32 + f) * NN + n0 + tx] = l;
    }
}

// ---------------- mma.sync 3xBF16 GEMM, split-K=2 ----------------
// Block tile 128 x BN, K-stage 32, 8 warps (R=4 x C=2). blockIdx.z selects the
// K half (2048 each) and the partial output buffer. 87KB smem (BN=96) ->
// 2 CTAs/SM so barrier bubbles in one CTA are covered by the other.
template<int BN>
__global__ void __launch_bounds__(256, 2)
k_gemm_mma(const float* __restrict__ U, const float* __restrict__ psi,
           int usepsi, int sel, int ldc)
{
    extern __shared__ __align__(16) char sm[];
    constexpr int AP   = 80;                 // 64B row + 16 pad -> conflict-free ldmatrix
    constexpr int ASZ  = 128 * AP;           // one A operand (hi or lo)
    constexpr int ASTG = 2 * ASZ;            // A stage: Ahi | Alo
    constexpr int BSZ  = BN * AP;
    constexpr int BSTG = 2 * BSZ;            // B stage: Bhi | Blo
    constexpr int BOFF = 2 * ASTG;           // B region after 2 A stages
    constexpr int CW   = BN / 2;             // cols per warp
    constexpr int NT   = CW / 8;
    constexpr int NP   = NT / 2;
    constexpr int BCHK = BN * 4;             // 16B chunks per operand per stage
    constexpr int NIT  = 64;                 // 2048 / 32

    const int tid = threadIdx.x;
    const int warp = tid >> 5, lane = tid & 31;
    const int rw = warp & 3;                 // row group (32 rows)
    const int chh = warp >> 2;               // N half
    const int K = 4096;
    const int row0 = blockIdx.x * 128;
    const int col0 = blockIdx.y * BN;
    const int k0 = blockIdx.z * 2048;
    const float* __restrict__ A = ((usepsi && row0 >= NN) ? psi + (size_t)(row0 - NN) * K
                                                          : U + (size_t)row0 * K) + k0;
    const __nv_bfloat16 *Bh, *Bl;
    float* C;
    if (sel == 0)      { Bh = g_afh; Bl = g_afl; C = blockIdx.z ? g_g1b : g_g1a; }
    else if (sel == 1) { Bh = g_a1h; Bl = g_a1l; C = blockIdx.z ? g_g2b : g_g2a; }
    else               { Bh = g_b3h; Bl = g_b3l; C = blockIdx.z ? g_g3b : g_g3a; }

    float c[2][NT][4];
    #pragma unroll
    for (int m = 0; m < 2; m++)
        #pragma unroll
        for (int j = 0; j < NT; j++)
            #pragma unroll
            for (int q = 0; q < 4; q++) c[m][j][q] = 0.f;

    // per-thread A mapping over the 128x32 fp32 tile: 4 x float4, rows step 32
    const int am_r = tid >> 3;               // 0..31
    const int am_c = (tid & 7) * 4;          // 0..28

    float4 areg[4];
    #pragma unroll
    for (int i = 0; i < 4; i++)
        areg[i] = *reinterpret_cast<const float4*>(A + (size_t)(am_r + 32 * i) * K + am_c);

    uint32_t sbase = s2u(sm);

    // B(0) cp.async -> B stage 0
    #pragma unroll
    for (int i = 0; i < BN / 32; i++) {
        int q = tid + i * 256;
        int half = q >= BCHK;
        int qq = q - half * BCHK;
        int n = qq >> 2, c16 = qq & 3;
        const __nv_bfloat16* src = (half ? Bl : Bh) + (size_t)(col0 + n) * 4096 + k0 + c16 * 8;
        CP_ASYNC16(sbase + BOFF + half * BSZ + n * AP + c16 * 16, src);
    }
    CP_COMMIT();

    // STS A(0) into A stage 0
    #pragma unroll
    for (int i = 0; i < 4; i++) {
        int r = am_r + 32 * i;
        __nv_bfloat16 h0, h1, h2, h3, l0, l1, l2, l3;
        bf16split(areg[i].x, h0, l0); bf16split(areg[i].y, h1, l1);
        bf16split(areg[i].z, h2, l2); bf16split(areg[i].w, h3, l3);
        *reinterpret_cast<uint2*>(sm + r * AP + am_c * 2) = make_uint2(pk(h0, h1), pk(h2, h3));
        *reinterpret_cast<uint2*>(sm + ASZ + r * AP + am_c * 2) = make_uint2(pk(l0, l1), pk(l2, l3));
    }

    // A(1) prefetch + B(1) cp.async -> B stage 1
    #pragma unroll
    for (int i = 0; i < 4; i++)
        areg[i] = *reinterpret_cast<const float4*>(A + (size_t)(am_r + 32 * i) * K + 32 + am_c);
    #pragma unroll
    for (int i = 0; i < BN / 32; i++) {
        int q = tid + i * 256;
        int half = q >= BCHK;
        int qq = q - half * BCHK;
        int n = qq >> 2, c16 = qq & 3;
        const __nv_bfloat16* src = (half ? Bl : Bh) + (size_t)(col0 + n) * 4096 + k0 + 32 + c16 * 8;
        CP_ASYNC16(sbase + BOFF + BSTG + half * BSZ + n * AP + c16 * 16, src);
    }
    CP_COMMIT();

    // ldmatrix lane addressing (within-stage byte offsets)
    const int a_off0 = (rw * 32 + (lane & 15)) * AP + (lane >> 4) * 16;
    const int a_off1 = a_off0 + 16 * AP;
    const int b_off  = (chh * CW + (lane & 7) + ((lane >> 4) << 3)) * AP +
                       ((lane >> 3) & 1) * 16;

    int bs = 0;                                   // B stage for iter it (= it % 3)
    for (int it = 0; it < NIT; ++it) {
        CP_WAIT1();                               // B(it) landed (B(it+1) may fly)
        __syncthreads();                          // A(it) STS + prior-stage reads fenced

        char* abuf = sm + (it & 1) * ASTG;
        char* nbuf = sm + ((it + 1) & 1) * ASTG;
        uint32_t a0addr = s2u(abuf) + a_off0;
        uint32_t a1addr = s2u(abuf) + a_off1;
        uint32_t bhaddr = sbase + BOFF + bs * BSTG + b_off;
        uint32_t bladdr = bhaddr + BSZ;
        int bt = bs + 2; if (bt >= 3) bt -= 3;    // B stage for it+2

        #pragma unroll
        for (int ks = 0; ks < 2; ks++) {
            uint32_t x0h0, x0h1, x0h2, x0h3, x0l0, x0l1, x0l2, x0l3;
            uint32_t x1h0, x1h1, x1h2, x1h3, x1l0, x1l1, x1l2, x1l3;
            LDMX4(x0h0, x0h1, x0h2, x0h3, a0addr + ks * 32);
            LDMX4(x0l0, x0l1, x0l2, x0l3, a0addr + ASZ + ks * 32);
            LDMX4(x1h0, x1h1, x1h2, x1h3, a1addr + ks * 32);
            LDMX4(x1l0, x1l1, x1l2, x1l3, a1addr + ASZ + ks * 32);
            #pragma unroll
            for (int jp = 0; jp < NP; jp++) {
                uint32_t bh0, bh1, bh2, bh3, bl0, bl1, bl2, bl3;
                LDMX4(bh0, bh1, bh2, bh3, bhaddr + jp * (16 * AP) + ks * 32);
                LDMX4(bl0, bl1, bl2, bl3, bladdr + jp * (16 * AP) + ks * 32);
                MMA16816(c[0][2 * jp],     x0h0, x0h1, x0h2, x0h3, bh0, bh1);
                MMA16816(c[0][2 * jp],     x0h0, x0h1, x0h2, x0h3, bl0, bl1);
                MMA16816(c[0][2 * jp],     x0l0, x0l1, x0l2, x0l3, bh0, bh1);
                MMA16816(c[1][2 * jp],     x1h0, x1h1, x1h2, x1h3, bh0, bh1);
                MMA16816(c[1][2 * jp],     x1h0, x1h1, x1h2, x1h3, bl0, bl1);
                MMA16816(c[1][2 * jp],     x1l0, x1l1, x1l2, x1l3, bh0, bh1);
                MMA16816(c[0][2 * jp + 1], x0h0, x0h1, x0h2, x0h3, bh2, bh3);
                MMA16816(c[0][2 * jp + 1], x0h0, x0h1, x0h2, x0h3, bl2, bl3);
                MMA16816(c[0][2 * jp + 1], x0l0, x0l1, x0l2, x0l3, bh2, bh3);
                MMA16816(c[1][2 * jp + 1], x1h0, x1h1, x1h2, x1h3, bh2, bh3);
                MMA16816(c[1][2 * jp + 1], x1h0, x1h1, x1h2, x1h3, bl2, bl3);
                MMA16816(c[1][2 * jp + 1], x1l0, x1l1, x1l2, x1l3, bh2, bh3);
            }
            // interleaved pipeline work (disjoint smem stages, no barrier needed)
            if (ks == 0) {
                // STS A(it+1) into next A stage
                #pragma unroll
                for (int i = 0; i < 4; i++) {
                    int r = am_r + 32 * i;
                    __nv_bfloat16 h0, h1, h2, h3, l0, l1, l2, l3;
                    bf16split(areg[i].x, h0, l0); bf16split(areg[i].y, h1, l1);
                    bf16split(areg[i].z, h2, l2); bf16split(areg[i].w, h3, l3);
                    *reinterpret_cast<uint2*>(nbuf + r * AP + am_c * 2) =
                        make_uint2(pk(h0, h1), pk(h2, h3));
                    *reinterpret_cast<uint2*>(nbuf + ASZ + r * AP + am_c * 2) =
                        make_uint2(pk(l0, l1), pk(l2, l3));
                }
            } else {
                if (it < NIT - 2) {
                    int kt = (it + 2) * 32;
                    #pragma unroll
                    for (int i = 0; i < 4; i++)
                        areg[i] = *reinterpret_cast<const float4*>(
                            A + (size_t)(am_r + 32 * i) * K + kt + am_c);
                    uint32_t sb = sbase + BOFF + bt * BSTG;
                    #pragma unroll
                    for (int i = 0; i < BN / 32; i++) {
                        int q = tid + i * 256;
                        int half = q >= BCHK;
                        int qq = q - half * BCHK;
                        int n = qq >> 2, c16 = qq & 3;
                        const __nv_bfloat16* src = (half ? Bl : Bh) +
                            (size_t)(col0 + n) * 4096 + k0 + kt + c16 * 8;
                        CP_ASYNC16(sb + half * BSZ + n * AP + c16 * 16, src);
                    }
                }
                CP_COMMIT();                      // unconditional: keeps group count exact
            }
        }
        if (++bs == 3) bs = 0;
    }

    // epilogue
    #pragma unroll
    for (int m = 0; m < 2; m++) {
        int rlo = row0 + rw * 32 + m * 16 + lane / 4;
        int rhi = rlo + 8;
        #pragma unroll
        for (int j = 0; j < NT; j++) {
            int col = col0 + chh * CW + j * 8 + (lane & 3) * 2;
            *reinterpret_cast<float2*>(C + (size_t)rlo * ldc + col) =
                make_float2(c[m][j][0], c[m][j][1]);
            *reinterpret_cast<float2*>(C + (size_t)rhi * ldc + col) =
                make_float2(c[m][j][2], c[m][j][3]);
        }
    }
}

// ---------------- CSR build (by dst, with self loops) ----------------
__global__ void k_csr_init() {
    int i = blockIdx.x * 256 + threadIdx.x;
    if (i < NN) g_cur[i] = 1;
}

__global__ void k_csr_hist(const int* __restrict__ ei) {
    int i = blockIdx.x * 256 + threadIdx.x;
    atomicAdd(&g_cur[ei[EE + i]], 1);
}

__global__ void __launch_bounds__(1024) k_csr_scan() {
    int t = threadIdx.x;
    int b = t * 4;
    int c0 = g_cur[b], c1 = g_cur[b + 1], c2 = g_cur[b + 2], c3 = g_cur[b + 3];
    int s1 = c0 + c1, s2 = s1 + c2, tot = s2 + c3;
    int lane = t & 31, wid = t >> 5;
    int x = tot;
    #pragma unroll
    for (int o = 1; o < 32; o <<= 1) {
        int y = __shfl_up_sync(0xffffffffu, x, o);
        if (lane >= o) x += y;
    }
    __shared__ int ws[32];
    if (lane == 31) ws[wid] = x;
    __syncthreads();
    if (wid == 0) {
        int y = ws[lane];
        #pragma unroll
        for (int o = 1; o < 32; o <<= 1) {
            int z = __shfl_up_sync(0xffffffffu, y, o);
            if (lane >= o) y += z;
        }
        ws[lane] = y;
    }
    __syncthreads();
    int excl = x - tot + (wid ? ws[wid - 1] : 0);
    g_off[b] = excl; g_off[b + 1] = excl + c0; g_off[b + 2] = excl + s1; g_off[b + 3] = excl + s2;
    g_cur[b] = excl; g_cur[b + 1] = excl + c0; g_cur[b + 2] = excl + s1; g_cur[b + 3] = excl + s2;
    if (t == 1023) g_off[NN] = excl + tot;
}

__global__ void k_csr_scatter(const int* __restrict__ ei) {
    int i = blockIdx.x * 256 + threadIdx.x;
    int s, d;
    if (i < EE) { s = ei[i]; d = ei[EE + i]; }
    else        { s = d = i - EE; }
    int pos = atomicAdd(&g_cur[d], 1);
    g_csrc[pos] = s;
}

// ---------------- GAT h/es/ed: warp-per-16-nodes, reads split buffers -------
__global__ void __launch_bounds__(256)
k_h(const float* __restrict__ gat_W, const float* __restrict__ att_src,
    const float* __restrict__ att_dst)
{
    int g = blockIdx.y;
    int warp = threadIdx.x >> 5, lane = threadIdx.x & 31;
    int n0 = (blockIdx.x * 8 + warp) * 16;
    float w0[32], w1[32];
    #pragma unroll
    for (int k = 0; k < 32; k++) {
        w0[k] = gat_W[(size_t)g * 2048 + k * 64 + lane];
        w1[k] = gat_W[(size_t)g * 2048 + k * 64 + lane + 32];
    }
    float as0 = att_src[g * 64 + lane], as1 = att_src[g * 64 + lane + 32];
    float ad0 = att_dst[g * 64 + lane], ad1 = att_dst[g * 64 + lane + 32];
    for (int t = 0; t < 16; t++) {
        int n = n0 + t;
        float cof;
        if (g == 0) {
            size_t idx = (size_t)n * FF + lane;
            cof = g_g1a[idx] + g_g1b[idx];
        } else if (g < 4) {
            size_t idx = (size_t)n * 96 + (g - 1) * 32 + lane;
            cof = g_g2a[idx] + g_g2b[idx];
        } else {
            size_t idx = (size_t)n * 288 + (g - 4) * 32 + lane;
            cof = g_g3a[idx] + g_g3b[idx];
        }
        float acc0 = 0.f, acc1 = 0.f;
        #pragma unroll
        for (int k = 0; k < 32; k++) {
            float c = __shfl_sync(0xffffffffu, cof, k);
            acc0 += w0[k] * c;
            acc1 += w1[k] * c;
        }
        g_h[((size_t)g * NN + n) * HF + lane]      = acc0;
        g_h[((size_t)g * NN + n) * HF + lane + 32] = acc1;
        float vs0 = acc0 * as0, vs1 = acc1 * as1;
        float vd0 = acc0 * ad0, vd1 = acc1 * ad1;
        #pragma unroll
        for (int o = 16; o; o >>= 1) {
            vs0 += __shfl_xor_sync(0xffffffffu, vs0, o);
            vs1 += __shfl_xor_sync(0xffffffffu, vs1, o);
            vd0 += __shfl_xor_sync(0xffffffffu, vd0, o);
            vd1 += __shfl_xor_sync(0xffffffffu, vd1, o);
        }
        if (lane == 0) {
            *reinterpret_cast<float2*>(&g_es[((size_t)g * NN + n) * 2]) = make_float2(vs0, vs1);
            *reinterpret_cast<float2*>(&g_ed[((size_t)g * NN + n) * 2]) = make_float2(vd0, vd1);
        }
    }
}

// ---------------- GAT aggregation + branch MLP (Round-8 known-good) --------
__global__ void __launch_bounds__(64)
k_agg(const float* __restrict__ gat_b, const float* __restrict__ mlp_W,
      const float* __restrict__ mlp_b)
{
    int n = blockIdx.x, g = blockIdx.y;
    int tid = threadIdx.x;
    int lane = tid & 31;
    int head = tid >> 5;
    int beg = g_off[n];
    int deg = g_off[n + 1] - beg;
    float2 edn = *reinterpret_cast<const float2*>(&g_ed[((size_t)g * NN + n) * 2]);

    float m0 = -1e30f, m1 = -1e30f;
    for (int i = tid; i < deg; i += 64) {
        int s = g_csrc[beg + i];
        float2 e = *reinterpret_cast<const float2*>(&g_es[((size_t)g * NN + s) * 2]);
        float e0 = e.x + edn.x; e0 = e0 > 0.f ? e0 : 0.2f * e0;
        float e1 = e.y + edn.y; e1 = e1 > 0.f ? e1 : 0.2f * e1;
        m0 = fmaxf(m0, e0); m1 = fmaxf(m1, e1);
    }
    #pragma unroll
    for (int o = 16; o; o >>= 1) {
        m0 = fmaxf(m0, __shfl_xor_sync(0xffffffffu, m0, o));
        m1 = fmaxf(m1, __shfl_xor_sync(0xffffffffu, m1, o));
    }
    __shared__ float pm0[2], pm1[2];
    if (lane == 0) { pm0[head] = m0; pm1[head] = m1; }
    __syncthreads();
    m0 = fmaxf(pm0[0], pm0[1]);
    m1 = fmaxf(pm1[0], pm1[1]);

    __shared__ float wbuf[2][32];
    __shared__ int   sbuf[32];
    float acc = 0.f, zp0 = 0.f, zp1 = 0.f;
    const float* hb = &g_h[(size_t)g * NN * HF];
    for (int c = 0; c < deg; c += 32) {
        __syncthreads();
        if (tid < 32) {
            int i = c + lane;
            float w0 = 0.f, w1 = 0.f; int s = 0;
            if (i < deg) {
                s = g_csrc[beg + i];
                float2 e = *reinterpret_cast<const float2*>(&g_es[((size_t)g * NN + s) * 2]);
                float e0 = e.x + edn.x; e0 = e0 > 0.f ? e0 : 0.2f * e0;
                float e1 = e.y + edn.y; e1 = e1 > 0.f ? e1 : 0.2f * e1;
                w0 = expf(e0 - m0); w1 = expf(e1 - m1);
            }
            wbuf[0][lane] = w0; wbuf[1][lane] = w1; sbuf[lane] = s;
            zp0 += w0; zp1 += w1;
        }
        __syncthreads();
        int lim = min(32, deg - c);
        for (int i = 0; i < lim; i++)
            acc += wbuf[head][i] * hb[(size_t)sbuf[i] * HF + tid];
    }
    __shared__ float sz[2];
    if (tid < 32) {
        #pragma unroll
        for (int o = 16; o; o >>= 1) {
            zp0 += __shfl_xor_sync(0xffffffffu, zp0, o);
            zp1 += __shfl_xor_sync(0xffffffffu, zp1, o);
        }
        if (lane == 0) { sz[0] = zp0; sz[1] = zp1; }
    }
    __syncthreads();
    float v = acc / (sz[head] + 1e-16f) + gat_b[g * HF + tid];
    v = v > 0.f ? v : expm1f(v);
    __shared__ float sh[64];
    sh[tid] = v;
    __syncthreads();
    float o = mlp_b[g * HF + tid];
    const float* mw = mlp_W + (size_t)g * HF * HF + tid;
    #pragma unroll 8
    for (int k = 0; k < 64; k++) o += sh[k] * mw[k * 64];
    g_feat[(size_t)n * (GG * HF) + g * HF + tid] = o;
}

// ---------------- final head + log_softmax ----------------
__global__ void __launch_bounds__(128)
k_out(const float* __restrict__ out_W, const float* __restrict__ out_b,
      float* __restrict__ out)
{
    int node = blockIdx.x * 4 + (threadIdx.x >> 5);
    int lane = threadIdx.x & 31;
    float acc[CC];
    #pragma unroll
    for (int c = 0; c < CC; c++) acc[c] = 0.f;
    const float* fr = &g_feat[(size_t)node * (GG * HF)];
    for (int k = lane; k < GG * HF; k += 32) {
        float v = fr[k];
        v = v > 0.f ? v : expm1f(v);
        #pragma unroll
        for (int c = 0; c < CC; c++) acc[c] += v * out_W[k * CC + c];
    }
    #pragma unroll
    for (int c = 0; c < CC; c++) {
        #pragma unroll
        for (int o = 16; o; o >>= 1)
            acc[c] += __shfl_xor_sync(0xffffffffu, acc[c], o);
        acc[c] += out_b[c];
    }
    float m = acc[0];
    #pragma unroll
    for (int c = 1; c < CC; c++) m = fmaxf(m, acc[c]);
    float s = 0.f;
    #pragma unroll
    for (int c = 0; c < CC; c++) s += expf(acc[c] - m);
    float lse = m + logf(s);
    if (lane < CC) out[(size_t)node * CC + lane] = acc[lane] - lse;
}

// ---------------- launcher ----------------
extern "C" void kernel_launch(void* const* d_in, const int* in_sizes, int n_in,
                              void* d_out, int out_size)
{
    const float* x       = (const float*)d_in[0];
    const int*   ei      = (const int*)  d_in[1];
    const float* U       = (const float*)d_in[2];
    const float* psi     = (const float*)d_in[3];
    const float* gat_W   = (const float*)d_in[4];
    const float* att_src = (const float*)d_in[5];
    const float* att_dst = (const float*)d_in[6];
    const float* gat_b   = (const float*)d_in[7];
    const float* mlp_W   = (const float*)d_in[8];
    const float* mlp_b   = (const float*)d_in[9];
    const float* out_W   = (const float*)d_in[10];
    const float* out_b   = (const float*)d_in[11];
    float* out = (float*)d_out;

    // smem: 2 A stages (2*2*128*80) + 3 B stages (3*2*BN*80)
    constexpr int SM32 = 4 * 128 * 80 + 6 * 32 * 80;    // 56320
    constexpr int SM96 = 4 * 128 * 80 + 6 * 96 * 80;    // 87040
    cudaFuncSetAttribute((const void*)k_gemm_mma<32>,
                         cudaFuncAttributeMaxDynamicSharedMemorySize, SM32);
    cudaFuncSetAttribute((const void*)k_gemm_mma<96>,
                         cudaFuncAttributeMaxDynamicSharedMemorySize, SM96);

    // scattering-tree GEMM chain first (mma.sync, 3xBF16, split-K=2)
    k_absT<<<128, dim3(32, 8)>>>(x);
    k_gemm_mma<32><<<dim3(128, 1, 2), 256, SM32>>>(U, psi, 1, 0, 32);   // [U;psi]@af
    k_a1T<<<dim3(128, 3), dim3(32, 8)>>>();
    k_gemm_mma<96><<<dim3(128, 1, 2), 256, SM96>>>(U, psi, 1, 1, 96);   // [U;psi]@|y1|
    k_b3T<<<dim3(128, 9), dim3(32, 8)>>>();
    k_gemm_mma<96><<<dim3(32, 3, 2), 256, SM96>>>(U, psi, 0, 2, 288);   // U@|y2|

    // CSR build (only needed before k_agg)
    k_csr_init<<<16, 256>>>();
    k_csr_hist<<<EE / 256, 256>>>(ei);
    k_csr_scan<<<1, 1024>>>();
    k_csr_scatter<<<ETOT / 256, 256>>>(ei);

    // GAT branches + MLPs (k_h reads split-K partials directly; no k_coefs)
    k_h<<<dim3(NN / 128, GG), 256>>>(gat_W, att_src, att_dst);
    k_agg<<<dim3(NN, GG), 64>>>(gat_b, mlp_W, mlp_b);

    // final head + log_softmax
    k_out<<<NN / 4, 128>>>(out_W, out_b, out);
}

// round 11
// speedup vs baseline: 1.0749x; 1.0272x over previous
#include <cuda_runtime.h>
#include <cuda_bf16.h>
#include <cstdint>

#define NN 4096
#define FF 32
#define HF 64
#define CC 10
#define GG 13
#define EE 65536
#define ETOT (EE + NN)   // 69632

// ---------------- scratch (static __device__, no allocation) ----------------
// split-K partial outputs (a = K[0:2048), b = K[2048:4096))
static __device__ __align__(16) float g_g1a[4 * NN * FF], g_g1b[4 * NN * FF];
static __device__ __align__(16) float g_g2a[4 * NN * 96], g_g2b[4 * NN * 96];
static __device__ __align__(16) float g_g3a[NN * 288],    g_g3b[NN * 288];
static __device__ __align__(16) __nv_bfloat16 g_afh[32 * NN],  g_afl[32 * NN];   // |x|^T split
static __device__ __align__(16) __nv_bfloat16 g_a1h[96 * NN],  g_a1l[96 * NN];   // |y1|^T split
static __device__ __align__(16) __nv_bfloat16 g_b3h[288 * NN], g_b3l[288 * NN];  // |y2|^T split
static __device__ float g_h[(size_t)GG * NN * HF];           // GAT h per branch
static __device__ float g_es[GG * NN * 2];
static __device__ float g_ed[GG * NN * 2];
static __device__ float g_feat[(size_t)NN * GG * HF];        // concat branch MLP outputs
static __device__ int   g_off[NN + 1];
static __device__ int   g_cur[NN];
static __device__ int   g_csrc[ETOT];

// ---------------- helpers ----------------
__device__ __forceinline__ void bf16split(float v, __nv_bfloat16& h, __nv_bfloat16& l) {
    h = __float2bfloat16_rn(v);
    l = __float2bfloat16_rn(v - __bfloat162float(h));
}
__device__ __forceinline__ uint32_t pk(__nv_bfloat16 a, __nv_bfloat16 b) {
    __nv_bfloat162 t = __halves2bfloat162(a, b);
    return *reinterpret_cast<uint32_t*>(&t);
}
__device__ __forceinline__ uint32_t s2u(const void* p) {
    uint32_t a;
    asm("{ .reg .u64 t; cvta.to.shared.u64 t, %1; cvt.u32.u64 %0, t; }" : "=r"(a) : "l"(p));
    return a;
}

#define CP_ASYNC16(saddr, gaddr) \
    asm volatile("cp.async.cg.shared.global [%0], [%1], 16;" :: "r"(saddr), "l"(gaddr))
#define CP_COMMIT() asm volatile("cp.async.commit_group;" ::: "memory")
#define CP_WAIT1()  asm volatile("cp.async.wait_group 1;" ::: "memory")

#define LDMX4(r0, r1, r2, r3, a) \
    asm volatile("ldmatrix.sync.aligned.m8n8.x4.shared.b16 {%0,%1,%2,%3}, [%4];" \
                 : "=r"(r0), "=r"(r1), "=r"(r2), "=r"(r3) : "r"(a))
#define MMA16816(c, a0, a1, a2, a3, b0, b1) \
    asm volatile("mma.sync.aligned.m16n8k16.row.col.f32.bf16.bf16.f32 " \
                 "{%0,%1,%2,%3}, {%4,%5,%6,%7}, {%8,%9}, {%0,%1,%2,%3};" \
                 : "+f"((c)[0]), "+f"((c)[1]), "+f"((c)[2]), "+f"((c)[3]) \
                 : "r"(a0), "r"(a1), "r"(a2), "r"(a3), "r"(b0), "r"(b1))

// ---------------- transpose + abs + bf16-split repack kernels ----------------
__global__ void k_absT(const float* __restrict__ x) {
    __shared__ float s[32][33];
    int n0 = blockIdx.x * 32;
    int tx = threadIdx.x, ty = threadIdx.y;
    #pragma unroll
    for (int i = 0; i < 4; i++)
        s[ty + 8 * i][tx] = fabsf(x[(size_t)(n0 + ty + 8 * i) * 32 + tx]);
    __syncthreads();
    #pragma unroll
    for (int i = 0; i < 4; i++) {
        int f = ty + 8 * i;
        __nv_bfloat16 h, l; bf16split(s[tx][f], h, l);
        g_afh[(size_t)f * NN + n0 + tx] = h;
        g_afl[(size_t)f * NN + n0 + tx] = l;
    }
}

__global__ void k_a1T() {
    __shared__ float s[32][33];
    int n0 = blockIdx.x * 32, j = blockIdx.y;
    int tx = threadIdx.x, ty = threadIdx.y;
    #pragma unroll
    for (int i = 0; i < 4; i++) {
        size_t idx = ((size_t)(1 + j) * NN + n0 + ty + 8 * i) * 32 + tx;
        s[ty + 8 * i][tx] = fabsf(g_g1a[idx] + g_g1b[idx]);
    }
    __syncthreads();
    #pragma unroll
    for (int i = 0; i < 4; i++) {
        int f = ty + 8 * i;
        __nv_bfloat16 h, l; bf16split(s[tx][f], h, l);
        g_a1h[(size_t)(j * 32 + f) * NN + n0 + tx] = h;
        g_a1l[(size_t)(j * 32 + f) * NN + n0 + tx] = l;
    }
}

__global__ void k_b3T() {
    __shared__ float s[32][33];
    int n0 = blockIdx.x * 32, y = blockIdx.y;          // y = j*3 + k
    int j = y / 3, k = y - 3 * j;
    int tx = threadIdx.x, ty = threadIdx.y;
    #pragma unroll
    for (int i = 0; i < 4; i++) {
        size_t idx = ((size_t)(1 + k) * NN + n0 + ty + 8 * i) * 96 + j * 32 + tx;
        s[ty + 8 * i][tx] = fabsf(g_g2a[idx] + g_g2b[idx]);
    }
    __syncthreads();
    #pragma unroll
    for (int i = 0; i < 4; i++) {
        int f = ty + 8 * i;
        __nv_bfloat16 h, l; bf16split(s[tx][f], h, l);
        g_b3h[(size_t)(y * 32 + f) * NN + n0 + tx] = h;
        g_b3l[(size_t)(y * 32 + f) * NN + n0 + tx] = l;
    }
}

// ---------------- mma.sync 3xBF16 GEMM, split-K=2 ----------------
template<int BN>
__global__ void __launch_bounds__(256, 2)
k_gemm_mma(const float* __restrict__ U, const float* __restrict__ psi,
           int usepsi, int sel, int ldc)
{
    extern __shared__ __align__(16) char sm[];
    constexpr int AP   = 80;                 // 64B row + 16 pad -> conflict-free ldmatrix
    constexpr int ASZ  = 128 * AP;           // one A operand (hi or lo)
    constexpr int ASTG = 2 * ASZ;            // A stage: Ahi | Alo
    constexpr int BSZ  = BN * AP;
    constexpr int BSTG = 2 * BSZ;            // B stage: Bhi | Blo
    constexpr int BOFF = 2 * ASTG;           // B region after 2 A stages
    constexpr int CW   = BN / 2;             // cols per warp
    constexpr int NT   = CW / 8;
    constexpr int NP   = NT / 2;
    constexpr int BCHK = BN * 4;             // 16B chunks per operand per stage
    constexpr int NIT  = 64;                 // 2048 / 32

    const int tid = threadIdx.x;
    const int warp = tid >> 5, lane = tid & 31;
    const int rw = warp & 3;                 // row group (32 rows)
    const int chh = warp >> 2;               // N half
    const int K = 4096;
    const int row0 = blockIdx.x * 128;
    const int col0 = blockIdx.y * BN;
    const int k0 = blockIdx.z * 2048;
    const float* __restrict__ A = ((usepsi && row0 >= NN) ? psi + (size_t)(row0 - NN) * K
                                                          : U + (size_t)row0 * K) + k0;
    const __nv_bfloat16 *Bh, *Bl;
    float* C;
    if (sel == 0)      { Bh = g_afh; Bl = g_afl; C = blockIdx.z ? g_g1b : g_g1a; }
    else if (sel == 1) { Bh = g_a1h; Bl = g_a1l; C = blockIdx.z ? g_g2b : g_g2a; }
    else               { Bh = g_b3h; Bl = g_b3l; C = blockIdx.z ? g_g3b : g_g3a; }

    float c[2][NT][4];
    #pragma unroll
    for (int m = 0; m < 2; m++)
        #pragma unroll
        for (int j = 0; j < NT; j++)
            #pragma unroll
            for (int q = 0; q < 4; q++) c[m][j][q] = 0.f;

    // per-thread A mapping over the 128x32 fp32 tile: 4 x float4, rows step 32
    const int am_r = tid >> 3;               // 0..31
    const int am_c = (tid & 7) * 4;          // 0..28

    float4 areg[4];
    #pragma unroll
    for (int i = 0; i < 4; i++)
        areg[i] = *reinterpret_cast<const float4*>(A + (size_t)(am_r + 32 * i) * K + am_c);

    uint32_t sbase = s2u(sm);

    // B(0) cp.async -> B stage 0
    #pragma unroll
    for (int i = 0; i < BN / 32; i++) {
        int q = tid + i * 256;
        int half = q >= BCHK;
        int qq = q - half * BCHK;
        int n = qq >> 2, c16 = qq & 3;
        const __nv_bfloat16* src = (half ? Bl : Bh) + (size_t)(col0 + n) * 4096 + k0 + c16 * 8;
        CP_ASYNC16(sbase + BOFF + half * BSZ + n * AP + c16 * 16, src);
    }
    CP_COMMIT();

    // STS A(0) into A stage 0
    #pragma unroll
    for (int i = 0; i < 4; i++) {
        int r = am_r + 32 * i;
        __nv_bfloat16 h0, h1, h2, h3, l0, l1, l2, l3;
        bf16split(areg[i].x, h0, l0); bf16split(areg[i].y, h1, l1);
        bf16split(areg[i].z, h2, l2); bf16split(areg[i].w, h3, l3);
        *reinterpret_cast<uint2*>(sm + r * AP + am_c * 2) = make_uint2(pk(h0, h1), pk(h2, h3));
        *reinterpret_cast<uint2*>(sm + ASZ + r * AP + am_c * 2) = make_uint2(pk(l0, l1), pk(l2, l3));
    }

    // A(1) prefetch + B(1) cp.async -> B stage 1
    #pragma unroll
    for (int i = 0; i < 4; i++)
        areg[i] = *reinterpret_cast<const float4*>(A + (size_t)(am_r + 32 * i) * K + 32 + am_c);
    #pragma unroll
    for (int i = 0; i < BN / 32; i++) {
        int q = tid + i * 256;
        int half = q >= BCHK;
        int qq = q - half * BCHK;
        int n = qq >> 2, c16 = qq & 3;
        const __nv_bfloat16* src = (half ? Bl : Bh) + (size_t)(col0 + n) * 4096 + k0 + 32 + c16 * 8;
        CP_ASYNC16(sbase + BOFF + BSTG + half * BSZ + n * AP + c16 * 16, src);
    }
    CP_COMMIT();

    // ldmatrix lane addressing (within-stage byte offsets)
    const int a_off0 = (rw * 32 + (lane & 15)) * AP + (lane >> 4) * 16;
    const int a_off1 = a_off0 + 16 * AP;
    const int b_off  = (chh * CW + (lane & 7) + ((lane >> 4) << 3)) * AP +
                       ((lane >> 3) & 1) * 16;

    int bs = 0;                                   // B stage for iter it (= it % 3)
    for (int it = 0; it < NIT; ++it) {
        CP_WAIT1();                               // B(it) landed (B(it+1) may fly)
        __syncthreads();                          // A(it) STS + prior-stage reads fenced

        char* abuf = sm + (it & 1) * ASTG;
        char* nbuf = sm + ((it + 1) & 1) * ASTG;
        uint32_t a0addr = s2u(abuf) + a_off0;
        uint32_t a1addr = s2u(abuf) + a_off1;
        uint32_t bhaddr = sbase + BOFF + bs * BSTG + b_off;
        uint32_t bladdr = bhaddr + BSZ;
        int bt = bs + 2; if (bt >= 3) bt -= 3;    // B stage for it+2

        #pragma unroll
        for (int ks = 0; ks < 2; ks++) {
            uint32_t x0h0, x0h1, x0h2, x0h3, x0l0, x0l1, x0l2, x0l3;
            uint32_t x1h0, x1h1, x1h2, x1h3, x1l0, x1l1, x1l2, x1l3;
            LDMX4(x0h0, x0h1, x0h2, x0h3, a0addr + ks * 32);
            LDMX4(x0l0, x0l1, x0l2, x0l3, a0addr + ASZ + ks * 32);
            LDMX4(x1h0, x1h1, x1h2, x1h3, a1addr + ks * 32);
            LDMX4(x1l0, x1l1, x1l2, x1l3, a1addr + ASZ + ks * 32);
            #pragma unroll
            for (int jp = 0; jp < NP; jp++) {
                uint32_t bh0, bh1, bh2, bh3, bl0, bl1, bl2, bl3;
                LDMX4(bh0, bh1, bh2, bh3, bhaddr + jp * (16 * AP) + ks * 32);
                LDMX4(bl0, bl1, bl2, bl3, bladdr + jp * (16 * AP) + ks * 32);
                MMA16816(c[0][2 * jp],     x0h0, x0h1, x0h2, x0h3, bh0, bh1);
                MMA16816(c[0][2 * jp],     x0h0, x0h1, x0h2, x0h3, bl0, bl1);
                MMA16816(c[0][2 * jp],     x0l0, x0l1, x0l2, x0l3, bh0, bh1);
                MMA16816(c[1][2 * jp],     x1h0, x1h1, x1h2, x1h3, bh0, bh1);
                MMA16816(c[1][2 * jp],     x1h0, x1h1, x1h2, x1h3, bl0, bl1);
                MMA16816(c[1][2 * jp],     x1l0, x1l1, x1l2, x1l3, bh0, bh1);
                MMA16816(c[0][2 * jp + 1], x0h0, x0h1, x0h2, x0h3, bh2, bh3);
                MMA16816(c[0][2 * jp + 1], x0h0, x0h1, x0h2, x0h3, bl2, bl3);
                MMA16816(c[0][2 * jp + 1], x0l0, x0l1, x0l2, x0l3, bh2, bh3);
                MMA16816(c[1][2 * jp + 1], x1h0, x1h1, x1h2, x1h3, bh2, bh3);
                MMA16816(c[1][2 * jp + 1], x1h0, x1h1, x1h2, x1h3, bl2, bl3);
                MMA16816(c[1][2 * jp + 1], x1l0, x1l1, x1l2, x1l3, bh2, bh3);
            }
            // interleaved pipeline work (disjoint smem stages, no barrier needed)
            if (ks == 0) {
                #pragma unroll
                for (int i = 0; i < 4; i++) {
                    int r = am_r + 32 * i;
                    __nv_bfloat16 h0, h1, h2, h3, l0, l1, l2, l3;
                    bf16split(areg[i].x, h0, l0); bf16split(areg[i].y, h1, l1);
                    bf16split(areg[i].z, h2, l2); bf16split(areg[i].w, h3, l3);
                    *reinterpret_cast<uint2*>(nbuf + r * AP + am_c * 2) =
                        make_uint2(pk(h0, h1), pk(h2, h3));
                    *reinterpret_cast<uint2*>(nbuf + ASZ + r * AP + am_c * 2) =
                        make_uint2(pk(l0, l1), pk(l2, l3));
                }
            } else {
                if (it < NIT - 2) {
                    int kt = (it + 2) * 32;
                    #pragma unroll
                    for (int i = 0; i < 4; i++)
                        areg[i] = *reinterpret_cast<const float4*>(
                            A + (size_t)(am_r + 32 * i) * K + kt + am_c);
                    uint32_t sb = sbase + BOFF + bt * BSTG;
                    #pragma unroll
                    for (int i = 0; i < BN / 32; i++) {
                        int q = tid + i * 256;
                        int half = q >= BCHK;
                        int qq = q - half * BCHK;
                        int n = qq >> 2, c16 = qq & 3;
                        const __nv_bfloat16* src = (half ? Bl : Bh) +
                            (size_t)(col0 + n) * 4096 + k0 + kt + c16 * 8;
                        CP_ASYNC16(sb + half * BSZ + n * AP + c16 * 16, src);
                    }
                }
                CP_COMMIT();                      // unconditional: keeps group count exact
            }
        }
        if (++bs == 3) bs = 0;
    }

    // epilogue
    #pragma unroll
    for (int m = 0; m < 2; m++) {
        int rlo = row0 + rw * 32 + m * 16 + lane / 4;
        int rhi = rlo + 8;
        #pragma unroll
        for (int j = 0; j < NT; j++) {
            int col = col0 + chh * CW + j * 8 + (lane & 3) * 2;
            *reinterpret_cast<float2*>(C + (size_t)rlo * ldc + col) =
                make_float2(c[m][j][0], c[m][j][1]);
            *reinterpret_cast<float2*>(C + (size_t)rhi * ldc + col) =
                make_float2(c[m][j][2], c[m][j][3]);
        }
    }
}

// ---------------- CSR build (by dst, with self loops) ----------------
__global__ void k_csr_init() {
    int i = blockIdx.x * 256 + threadIdx.x;
    if (i < NN) g_cur[i] = 1;
}

__global__ void k_csr_hist(const int* __restrict__ ei) {
    int i = blockIdx.x * 256 + threadIdx.x;
    atomicAdd(&g_cur[ei[EE + i]], 1);
}

__global__ void __launch_bounds__(1024) k_csr_scan() {
    int t = threadIdx.x;
    int b = t * 4;
    int c0 = g_cur[b], c1 = g_cur[b + 1], c2 = g_cur[b + 2], c3 = g_cur[b + 3];
    int s1 = c0 + c1, s2 = s1 + c2, tot = s2 + c3;
    int lane = t & 31, wid = t >> 5;
    int x = tot;
    #pragma unroll
    for (int o = 1; o < 32; o <<= 1) {
        int y = __shfl_up_sync(0xffffffffu, x, o);
        if (lane >= o) x += y;
    }
    __shared__ int ws[32];
    if (lane == 31) ws[wid] = x;
    __syncthreads();
    if (wid == 0) {
        int y = ws[lane];
        #pragma unroll
        for (int o = 1; o < 32; o <<= 1) {
            int z = __shfl_up_sync(0xffffffffu, y, o);
            if (lane >= o) y += z;
        }
        ws[lane] = y;
    }
    __syncthreads();
    int excl = x - tot + (wid ? ws[wid - 1] : 0);
    g_off[b] = excl; g_off[b + 1] = excl + c0; g_off[b + 2] = excl + s1; g_off[b + 3] = excl + s2;
    g_cur[b] = excl; g_cur[b + 1] = excl + c0; g_cur[b + 2] = excl + s1; g_cur[b + 3] = excl + s2;
    if (t == 1023) g_off[NN] = excl + tot;
}

__global__ void k_csr_scatter(const int* __restrict__ ei) {
    int i = blockIdx.x * 256 + threadIdx.x;
    int s, d;
    if (i < EE) { s = ei[i]; d = ei[EE + i]; }
    else        { s = d = i - EE; }
    int pos = atomicAdd(&g_cur[d], 1);
    g_csrc[pos] = s;
}

// ---------------- GAT h/es/ed: warp-per-16-nodes, reads split buffers -------
__global__ void __launch_bounds__(256)
k_h(const float* __restrict__ gat_W, const float* __restrict__ att_src,
    const float* __restrict__ att_dst)
{
    int g = blockIdx.y;
    int warp = threadIdx.x >> 5, lane = threadIdx.x & 31;
    int n0 = (blockIdx.x * 8 + warp) * 16;
    float w0[32], w1[32];
    #pragma unroll
    for (int k = 0; k < 32; k++) {
        w0[k] = gat_W[(size_t)g * 2048 + k * 64 + lane];
        w1[k] = gat_W[(size_t)g * 2048 + k * 64 + lane + 32];
    }
    float as0 = att_src[g * 64 + lane], as1 = att_src[g * 64 + lane + 32];
    float ad0 = att_dst[g * 64 + lane], ad1 = att_dst[g * 64 + lane + 32];
    for (int t = 0; t < 16; t++) {
        int n = n0 + t;
        float cof;
        if (g == 0) {
            size_t idx = (size_t)n * FF + lane;
            cof = g_g1a[idx] + g_g1b[idx];
        } else if (g < 4) {
            size_t idx = (size_t)n * 96 + (g - 1) * 32 + lane;
            cof = g_g2a[idx] + g_g2b[idx];
        } else {
            size_t idx = (size_t)n * 288 + (g - 4) * 32 + lane;
            cof = g_g3a[idx] + g_g3b[idx];
        }
        float acc0 = 0.f, acc1 = 0.f;
        #pragma unroll
        for (int k = 0; k < 32; k++) {
            float c = __shfl_sync(0xffffffffu, cof, k);
            acc0 += w0[k] * c;
            acc1 += w1[k] * c;
        }
        g_h[((size_t)g * NN + n) * HF + lane]      = acc0;
        g_h[((size_t)g * NN + n) * HF + lane + 32] = acc1;
        float vs0 = acc0 * as0, vs1 = acc1 * as1;
        float vd0 = acc0 * ad0, vd1 = acc1 * ad1;
        #pragma unroll
        for (int o = 16; o; o >>= 1) {
            vs0 += __shfl_xor_sync(0xffffffffu, vs0, o);
            vs1 += __shfl_xor_sync(0xffffffffu, vs1, o);
            vd0 += __shfl_xor_sync(0xffffffffu, vd0, o);
            vd1 += __shfl_xor_sync(0xffffffffu, vd1, o);
        }
        if (lane == 0) {
            *reinterpret_cast<float2*>(&g_es[((size_t)g * NN + n) * 2]) = make_float2(vs0, vs1);
            *reinterpret_cast<float2*>(&g_ed[((size_t)g * NN + n) * 2]) = make_float2(vd0, vd1);
        }
    }
}

// ---------------- GAT aggregation + branch MLP: warp per node ---------------
// Lane-parallel 2-pass softmax (Round-8 structure, warp-level via shfl) +
// smem-cached mlp_W (16KB loaded once per 16-node block; kills the ~870MB of
// strided global W traffic the 64-thread version generated).
__global__ void __launch_bounds__(256)
k_agg(const float* __restrict__ gat_b, const float* __restrict__ mlp_W,
      const float* __restrict__ mlp_b)
{
    int g = blockIdx.y;
    int warp = threadIdx.x >> 5, lane = threadIdx.x & 31;

    __shared__ float Ws[64 * 64];
    __shared__ float gbs[64], mbs[64];
    for (int i = threadIdx.x; i < 64 * 64; i += 256)
        Ws[i] = mlp_W[(size_t)g * 4096 + i];
    if (threadIdx.x < 64) {
        gbs[threadIdx.x] = gat_b[g * 64 + threadIdx.x];
        mbs[threadIdx.x] = mlp_b[g * 64 + threadIdx.x];
    }
    __syncthreads();

    const float* hb = &g_h[(size_t)g * NN * HF];
    for (int t = 0; t < 2; t++) {
        int n = blockIdx.x * 16 + warp * 2 + t;
        int beg = g_off[n], deg = g_off[n + 1] - beg;
        float2 edn = *reinterpret_cast<const float2*>(&g_ed[((size_t)g * NN + n) * 2]);

        // pass 1: per-head segment max (lane-parallel over edges)
        float m0 = -1e30f, m1 = -1e30f;
        for (int i = lane; i < deg; i += 32) {
            int s = g_csrc[beg + i];
            float2 e = *reinterpret_cast<const float2*>(&g_es[((size_t)g * NN + s) * 2]);
            float e0 = e.x + edn.x; e0 = e0 > 0.f ? e0 : 0.2f * e0;
            float e1 = e.y + edn.y; e1 = e1 > 0.f ? e1 : 0.2f * e1;
            m0 = fmaxf(m0, e0); m1 = fmaxf(m1, e1);
        }
        #pragma unroll
        for (int o = 16; o; o >>= 1) {
            m0 = fmaxf(m0, __shfl_xor_sync(0xffffffffu, m0, o));
            m1 = fmaxf(m1, __shfl_xor_sync(0xffffffffu, m1, o));
        }

        // pass 2: lane-parallel exp, shfl-broadcast (w,s), coalesced h gathers
        float z0 = 0.f, z1 = 0.f, acc0 = 0.f, acc1 = 0.f;
        for (int c = 0; c < deg; c += 32) {
            int i = c + lane;
            float w0 = 0.f, w1 = 0.f; int s = 0;
            if (i < deg) {
                s = g_csrc[beg + i];
                float2 e = *reinterpret_cast<const float2*>(&g_es[((size_t)g * NN + s) * 2]);
                float e0 = e.x + edn.x; e0 = e0 > 0.f ? e0 : 0.2f * e0;
                float e1 = e.y + edn.y; e1 = e1 > 0.f ? e1 : 0.2f * e1;
                w0 = expf(e0 - m0); w1 = expf(e1 - m1);
            }
            z0 += w0; z1 += w1;
            int lim = min(32, deg - c);
            for (int j = 0; j < lim; j++) {
                float wj0 = __shfl_sync(0xffffffffu, w0, j);
                float wj1 = __shfl_sync(0xffffffffu, w1, j);
                int   sj  = __shfl_sync(0xffffffffu, s,  j);
                acc0 += wj0 * hb[(size_t)sj * HF + lane];
                acc1 += wj1 * hb[(size_t)sj * HF + lane + 32];
            }
        }
        #pragma unroll
        for (int o = 16; o; o >>= 1) {
            z0 += __shfl_xor_sync(0xffffffffu, z0, o);
            z1 += __shfl_xor_sync(0xffffffffu, z1, o);
        }

        float v0 = acc0 / (z0 + 1e-16f) + gbs[lane];
        float v1 = acc1 / (z1 + 1e-16f) + gbs[lane + 32];
        v0 = v0 > 0.f ? v0 : expm1f(v0);
        v1 = v1 > 0.f ? v1 : expm1f(v1);

        float oA = mbs[lane], oB = mbs[lane + 32];
        #pragma unroll
        for (int k = 0; k < 32; k++) {
            float c0 = __shfl_sync(0xffffffffu, v0, k);
            float c1 = __shfl_sync(0xffffffffu, v1, k);
            oA += c0 * Ws[k * 64 + lane]      + c1 * Ws[(k + 32) * 64 + lane];
            oB += c0 * Ws[k * 64 + lane + 32] + c1 * Ws[(k + 32) * 64 + lane + 32];
        }
        g_feat[(size_t)n * (GG * HF) + g * HF + lane]      = oA;
        g_feat[(size_t)n * (GG * HF) + g * HF + lane + 32] = oB;
    }
}

// ---------------- final head + log_softmax ----------------
__global__ void __launch_bounds__(128)
k_out(const float* __restrict__ out_W, const float* __restrict__ out_b,
      float* __restrict__ out)
{
    int node = blockIdx.x * 4 + (threadIdx.x >> 5);
    int lane = threadIdx.x & 31;
    float acc[CC];
    #pragma unroll
    for (int c = 0; c < CC; c++) acc[c] = 0.f;
    const float* fr = &g_feat[(size_t)node * (GG * HF)];
    for (int k = lane; k < GG * HF; k += 32) {
        float v = fr[k];
        v = v > 0.f ? v : expm1f(v);
        #pragma unroll
        for (int c = 0; c < CC; c++) acc[c] += v * out_W[k * CC + c];
    }
    #pragma unroll
    for (int c = 0; c < CC; c++) {
        #pragma unroll
        for (int o = 16; o; o >>= 1)
            acc[c] += __shfl_xor_sync(0xffffffffu, acc[c], o);
        acc[c] += out_b[c];
    }
    float m = acc[0];
    #pragma unroll
    for (int c = 1; c < CC; c++) m = fmaxf(m, acc[c]);
    float s = 0.f;
    #pragma unroll
    for (int c = 0; c < CC; c++) s += expf(acc[c] - m);
    float lse = m + logf(s);
    if (lane < CC) out[(size_t)node * CC + lane] = acc[lane] - lse;
}

// ---------------- launcher ----------------
extern "C" void kernel_launch(void* const* d_in, const int* in_sizes, int n_in,
                              void* d_out, int out_size)
{
    const float* x       = (const float*)d_in[0];
    const int*   ei      = (const int*)  d_in[1];
    const float* U       = (const float*)d_in[2];
    const float* psi     = (const float*)d_in[3];
    const float* gat_W   = (const float*)d_in[4];
    const float* att_src = (const float*)d_in[5];
    const float* att_dst = (const float*)d_in[6];
    const float* gat_b   = (const float*)d_in[7];
    const float* mlp_W   = (const float*)d_in[8];
    const float* mlp_b   = (const float*)d_in[9];
    const float* out_W   = (const float*)d_in[10];
    const float* out_b   = (const float*)d_in[11];
    float* out = (float*)d_out;

    // smem: 2 A stages (2*2*128*80) + 3 B stages (3*2*BN*80)
    constexpr int SM32 = 4 * 128 * 80 + 6 * 32 * 80;    // 56320
    constexpr int SM96 = 4 * 128 * 80 + 6 * 96 * 80;    // 87040
    cudaFuncSetAttribute((const void*)k_gemm_mma<32>,
                         cudaFuncAttributeMaxDynamicSharedMemorySize, SM32);
    cudaFuncSetAttribute((const void*)k_gemm_mma<96>,
                         cudaFuncAttributeMaxDynamicSharedMemorySize, SM96);

    // scattering-tree GEMM chain first (mma.sync, 3xBF16, split-K=2)
    k_absT<<<128, dim3(32, 8)>>>(x);
    k_gemm_mma<32><<<dim3(128, 1, 2), 256, SM32>>>(U, psi, 1, 0, 32);   // [U;psi]@af
    k_a1T<<<dim3(128, 3), dim3(32, 8)>>>();
    k_gemm_mma<96><<<dim3(128, 1, 2), 256, SM96>>>(U, psi, 1, 1, 96);   // [U;psi]@|y1|
    k_b3T<<<dim3(128, 9), dim3(32, 8)>>>();
    k_gemm_mma<96><<<dim3(32, 3, 2), 256, SM96>>>(U, psi, 0, 2, 288);   // U@|y2|

    // CSR build (only needed before k_agg)
    k_csr_init<<<16, 256>>>();
    k_csr_hist<<<EE / 256, 256>>>(ei);
    k_csr_scan<<<1, 1024>>>();
    k_csr_scatter<<<ETOT / 256, 256>>>(ei);

    // GAT branches + MLPs (k_h reads split-K partials directly; no k_coefs)
    k_h<<<dim3(NN / 128, GG), 256>>>(gat_W, att_src, att_dst);
    k_agg<<<dim3(NN / 16, GG), 256>>>(gat_b, mlp_W, mlp_b);

    // final head + log_softmax
    k_out<<<NN / 4, 128>>>(out_W, out_b, out);
}